// round 2
// baseline (speedup 1.0000x reference)
#include <cuda_runtime.h>

// Problem shapes (fixed by the dataset)
#define B_DIM 64
#define N_DIM 1024
#define C_DIM 256
#define TOK   64      // tokens per block (phase 1)
#define CODE_T 128    // codes per block tile
#define KC    32      // C-chunk staged in smem
#define ZS_STR 68
#define CB_STR 132
#define SMEM_FLOATS (C_DIM * ZS_STR + KC * CB_STR)
#define SMEM_BYTES  (SMEM_FLOATS * 4)
#define EPS_AMB 1e-3f
#define NTOK (B_DIM * N_DIM)
#define OUT_IDX ((size_t)B_DIM * N_DIM * C_DIM)
#define OUT_LOSS (OUT_IDX + (size_t)B_DIM * N_DIM)

// Device scratch (no cudaMalloc allowed)
__device__ float g_cnorm[3840];     // ||c_k||^2 (fp64-accurate, stored fp32)
__device__ float g_partial[1024];   // per-block SSE partials
__device__ int   g_idx[NTOK];       // per-token winning code
__device__ int   g_amb[NTOK];       // ambiguous token list
__device__ int   g_cnt;             // ambiguous count

__device__ __forceinline__ void pick_cb(int e, const float* cb0, const float* cb1,
                                        const float* cb2, const float* cb3,
                                        const float*& cb, int& K, int& coff)
{
    if (e == 0)      { cb = cb0; K = 256;  coff = 0;    }
    else if (e == 1) { cb = cb1; K = 512;  coff = 256;  }
    else if (e == 2) { cb = cb2; K = 1024; coff = 768;  }
    else             { cb = cb3; K = 2048; coff = 1792; }
}

// ---------------------------------------------------------------------------
// K0: codebook row norms in fp64 (rounded to fp32) + reset ambiguous counter
// ---------------------------------------------------------------------------
__global__ void cnorm_kernel(const float* __restrict__ cb0, const float* __restrict__ cb1,
                             const float* __restrict__ cb2, const float* __restrict__ cb3)
{
    if (blockIdx.x == 0 && threadIdx.x == 0) g_cnt = 0;
    int row  = blockIdx.x * 8 + (threadIdx.x >> 5);
    int lane = threadIdx.x & 31;
    const float* base; int local;
    if (row < 256)       { base = cb0; local = row;        }
    else if (row < 768)  { base = cb1; local = row - 256;  }
    else if (row < 1792) { base = cb2; local = row - 768;  }
    else                 { base = cb3; local = row - 1792; }
    const float4* p = (const float4*)(base + (size_t)local * C_DIM);
    double s = 0.0;
    #pragma unroll
    for (int i = 0; i < 2; i++) {
        float4 v = p[lane + i * 32];
        s += (double)v.x * v.x + (double)v.y * v.y + (double)v.z * v.z + (double)v.w * v.w;
    }
    #pragma unroll
    for (int o = 16; o; o >>= 1) s += __shfl_xor_sync(0xffffffffu, s, o);
    if (lane == 0) g_cnorm[row] = (float)s;
}

// ---------------------------------------------------------------------------
// K1: distance GEMM + top-2 argmin per token; flag ambiguous tokens
// ---------------------------------------------------------------------------
__global__ __launch_bounds__(256, 2) void vq_main(
    const float* __restrict__ z_e, const int* __restrict__ expert_idx,
    const float* __restrict__ cb0, const float* __restrict__ cb1,
    const float* __restrict__ cb2, const float* __restrict__ cb3)
{
    extern __shared__ float smem[];
    float* zs  = smem;
    float* cbs = smem + C_DIM * ZS_STR;

    const int tid = threadIdx.x;
    const int b   = blockIdx.y;
    const int t0  = blockIdx.x * TOK;

    const float* cb; int K, coff;
    pick_cb(expert_idx[b], cb0, cb1, cb2, cb3, cb, K, coff);

    const float4* zin = (const float4*)(z_e + ((size_t)b * N_DIM + t0) * C_DIM);

    for (int i = tid; i < TOK * (C_DIM / 4); i += 256) {
        int t = i >> 6, c4 = i & 63;
        float4 v = zin[(size_t)t * 64 + c4];
        int c = c4 * 4;
        zs[(c + 0) * ZS_STR + t] = v.x;
        zs[(c + 1) * ZS_STR + t] = v.y;
        zs[(c + 2) * ZS_STR + t] = v.z;
        zs[(c + 3) * ZS_STR + t] = v.w;
    }

    const int tx = tid & 15, ty = tid >> 4;
    float v1[4] = {3.4e38f, 3.4e38f, 3.4e38f, 3.4e38f};
    float v2[4] = {3.4e38f, 3.4e38f, 3.4e38f, 3.4e38f};
    int   i1[4] = {0, 0, 0, 0};

    for (int k0 = 0; k0 < K; k0 += CODE_T) {
        float acc[4][8];
        #pragma unroll
        for (int i = 0; i < 4; i++)
            #pragma unroll
            for (int j = 0; j < 8; j++) acc[i][j] = 0.f;

        for (int c0 = 0; c0 < C_DIM; c0 += KC) {
            __syncthreads();
            for (int i = tid; i < CODE_T * (KC / 4); i += 256) {
                int kk = i >> 3, c4 = i & 7;
                float4 v = *(const float4*)(cb + (size_t)(k0 + kk) * C_DIM + c0 + c4 * 4);
                int cc = c4 * 4;
                cbs[(cc + 0) * CB_STR + kk] = v.x;
                cbs[(cc + 1) * CB_STR + kk] = v.y;
                cbs[(cc + 2) * CB_STR + kk] = v.z;
                cbs[(cc + 3) * CB_STR + kk] = v.w;
            }
            __syncthreads();

            #pragma unroll
            for (int c = 0; c < KC; c++) {
                float4 rz = *(const float4*)&zs[(c0 + c) * ZS_STR + ty * 4];
                float4 ra = *(const float4*)&cbs[c * CB_STR + tx * 8];
                float4 rb = *(const float4*)&cbs[c * CB_STR + tx * 8 + 4];
                float zz[4] = {rz.x, rz.y, rz.z, rz.w};
                float kv[8] = {ra.x, ra.y, ra.z, ra.w, rb.x, rb.y, rb.z, rb.w};
                #pragma unroll
                for (int i = 0; i < 4; i++)
                    #pragma unroll
                    for (int j = 0; j < 8; j++)
                        acc[i][j] += zz[i] * kv[j];
            }
        }

        #pragma unroll
        for (int j = 0; j < 8; j++) {
            int k = k0 + tx * 8 + j;
            float cn = __ldg(&g_cnorm[coff + k]);
            #pragma unroll
            for (int i = 0; i < 4; i++) {
                float s = cn - 2.f * acc[i][j];
                if (s < v1[i]) { v2[i] = v1[i]; v1[i] = s; i1[i] = k; }
                else if (s < v2[i]) { v2[i] = s; }
            }
        }
    }

    // Merge top-2 across the 16 tx lanes
    #pragma unroll
    for (int o = 8; o; o >>= 1) {
        #pragma unroll
        for (int i = 0; i < 4; i++) {
            float ov1 = __shfl_xor_sync(0xffffffffu, v1[i], o);
            int   oi1 = __shfl_xor_sync(0xffffffffu, i1[i], o);
            float ov2 = __shfl_xor_sync(0xffffffffu, v2[i], o);
            float hi = fmaxf(v1[i], ov1);           // loser of the two mins
            float nv2 = fminf(fminf(v2[i], ov2), hi);
            if (ov1 < v1[i] || (ov1 == v1[i] && oi1 < i1[i])) { v1[i] = ov1; i1[i] = oi1; }
            v2[i] = nv2;
        }
    }
    if (tx == 0) {
        #pragma unroll
        for (int i = 0; i < 4; i++) {
            int tok = b * N_DIM + t0 + ty * 4 + i;
            g_idx[tok] = i1[i];
            if (v2[i] - v1[i] <= EPS_AMB) {
                int pos = atomicAdd(&g_cnt, 1);
                g_amb[pos] = tok;
            }
        }
    }
}

// ---------------------------------------------------------------------------
// K2: resolve ambiguous tokens by emulating the reference fp32 rounding:
//   d_k = fl(fl(zn + cn_k) - 2*dot_k)  ==  zn + RN_Gs(cn_k) - RN_Gd(2*dot_k)
// with dot_k = sequential ascending fp32 FMA chain (Eigen/cublas sgemm order).
// One warp per token; argmin with first-index tie-break.
// ---------------------------------------------------------------------------
__global__ __launch_bounds__(256) void resolve_kernel(
    const float* __restrict__ z_e, const int* __restrict__ expert_idx,
    const float* __restrict__ cb0, const float* __restrict__ cb1,
    const float* __restrict__ cb2, const float* __restrict__ cb3)
{
    __shared__ float zrow[8][C_DIM];
    const int wid = threadIdx.x >> 5, lane = threadIdx.x & 31;
    const int gw = blockIdx.x * 8 + wid;
    const int nw = gridDim.x * 8;
    const int cnt = g_cnt;

    for (int it = gw; it < cnt; it += nw) {
        int tok = g_amb[it];
        int b = tok >> 10;
        const float* cb; int K, coff;
        pick_cb(expert_idx[b], cb0, cb1, cb2, cb3, cb, K, coff);

        const float4* zr = (const float4*)(z_e + (size_t)tok * C_DIM);
        #pragma unroll
        for (int r = 0; r < 2; r++) {
            float4 v = zr[lane + r * 32];
            int c = (lane + r * 32) * 4;
            zrow[wid][c + 0] = v.x; zrow[wid][c + 1] = v.y;
            zrow[wid][c + 2] = v.z; zrow[wid][c + 3] = v.w;
        }
        __syncwarp();

        // zn in fp64 (only its binade matters)
        double zn = 0.0;
        #pragma unroll
        for (int c = 0; c < 8; c++) {
            double z = (double)zrow[wid][lane * 8 + c];
            zn += z * z;
        }
        #pragma unroll
        for (int o = 16; o; o >>= 1) zn += __shfl_xor_sync(0xffffffffu, zn, o);

        const double invGs = (zn >= 256.0) ? 32768.0 : 65536.0;
        const double Gs = 1.0 / invGs;

        double bestm = 1e300; int besti = 0x7fffffff;
        for (int k0 = 0; k0 < K; k0 += 32) {
            int k = k0 + lane;
            const float* cr = cb + (size_t)k * C_DIM;
            float acc = 0.f;
            #pragma unroll 8
            for (int c = 0; c < C_DIM; c++)
                acc = fmaf(zrow[wid][c], __ldg(&cr[c]), acc);  // dependent chain: fixed order
            float cn32 = __ldg(&g_cnorm[coff + k]);
            double dot2 = 2.0 * (double)acc;
            double d = zn + (double)cn32 - dot2;
            double invGd = (d >= 256.0) ? 32768.0 : 65536.0;
            double Gd = 1.0 / invGd;
            double m = rint((double)cn32 * invGs) * Gs - rint(dot2 * invGd) * Gd;
            if (m < bestm || (m == bestm && k < besti)) { bestm = m; besti = k; }
        }
        #pragma unroll
        for (int o = 16; o; o >>= 1) {
            double om = __shfl_xor_sync(0xffffffffu, bestm, o);
            int    oi = __shfl_xor_sync(0xffffffffu, besti, o);
            if (om < bestm || (om == bestm && oi < besti)) { bestm = om; besti = oi; }
        }
        if (lane == 0) g_idx[tok] = besti;
    }
}

// ---------------------------------------------------------------------------
// K3: gather z_q, straight-through rounding, indices output, SSE partials
// ---------------------------------------------------------------------------
__global__ __launch_bounds__(256) void output_kernel(
    const float* __restrict__ z_e, const int* __restrict__ expert_idx,
    const float* __restrict__ cb0, const float* __restrict__ cb1,
    const float* __restrict__ cb2, const float* __restrict__ cb3,
    float* __restrict__ out)
{
    __shared__ float wsum[8];
    const int tid = threadIdx.x;
    const int b   = blockIdx.y;
    const int t0  = blockIdx.x * TOK;

    const float* cb; int K, coff;
    pick_cb(expert_idx[b], cb0, cb1, cb2, cb3, cb, K, coff);

    const float4* zin = (const float4*)(z_e + ((size_t)b * N_DIM + t0) * C_DIM);

    if (tid < TOK) {
        int idx = g_idx[b * N_DIM + t0 + tid];
        out[OUT_IDX + (size_t)b * N_DIM + t0 + tid] = (float)idx;
    }

    const int warp = tid >> 5, lane = tid & 31;
    float sq = 0.f;
    for (int s8 = 0; s8 < 8; s8++) {
        int t = warp * 8 + s8;
        int idx = g_idx[b * N_DIM + t0 + t];
        const float4* crow = (const float4*)(cb + (size_t)idx * C_DIM);
        const float4* zrow = zin + (size_t)t * 64;
        float4* orow = (float4*)(out + ((size_t)b * N_DIM + t0 + t) * C_DIM);
        #pragma unroll
        for (int r = 0; r < 2; r++) {
            int c4 = lane + r * 32;
            float4 q = crow[c4], z = zrow[c4];
            float dx = q.x - z.x, dy = q.y - z.y, dz = q.z - z.z, dw = q.w - z.w;
            sq += dx * dx + dy * dy + dz * dz + dw * dw;
            float4 o; o.x = z.x + dx; o.y = z.y + dy; o.z = z.z + dz; o.w = z.w + dw;
            orow[c4] = o;
        }
    }
    #pragma unroll
    for (int o = 16; o; o >>= 1) sq += __shfl_xor_sync(0xffffffffu, sq, o);
    if (lane == 0) wsum[warp] = sq;
    __syncthreads();
    if (tid == 0) {
        float tot = 0.f;
        #pragma unroll
        for (int w = 0; w < 8; w++) tot += wsum[w];
        g_partial[blockIdx.y * 16 + blockIdx.x] = tot;
    }
}

// ---------------------------------------------------------------------------
// K4: vq_loss = 1.25 * SSE / 2^32
// ---------------------------------------------------------------------------
__global__ void finalize_kernel(float* __restrict__ out)
{
    __shared__ float s[256];
    float a = 0.f;
    for (int i = threadIdx.x; i < 1024; i += 256) a += g_partial[i];
    s[threadIdx.x] = a;
    __syncthreads();
    for (int o = 128; o; o >>= 1) {
        if (threadIdx.x < o) s[threadIdx.x] += s[threadIdx.x + o];
        __syncthreads();
    }
    if (threadIdx.x == 0)
        out[OUT_LOSS] = s[0] * (float)(1.25 / 4294967296.0);
}

// ---------------------------------------------------------------------------
extern "C" void kernel_launch(void* const* d_in, const int* in_sizes, int n_in,
                              void* d_out, int out_size)
{
    const float* z_e        = (const float*)d_in[0];
    const int*   expert_idx = (const int*)  d_in[1];
    const float* cb0        = (const float*)d_in[2];
    const float* cb1        = (const float*)d_in[3];
    const float* cb2        = (const float*)d_in[4];
    const float* cb3        = (const float*)d_in[5];
    float* out = (float*)d_out;

    cudaFuncSetAttribute(vq_main, cudaFuncAttributeMaxDynamicSharedMemorySize, SMEM_BYTES);

    cnorm_kernel<<<3840 / 8, 256>>>(cb0, cb1, cb2, cb3);

    dim3 grid(N_DIM / TOK, B_DIM);
    vq_main<<<grid, 256, SMEM_BYTES>>>(z_e, expert_idx, cb0, cb1, cb2, cb3);

    resolve_kernel<<<128, 256>>>(z_e, expert_idx, cb0, cb1, cb2, cb3);

    output_kernel<<<grid, 256>>>(z_e, expert_idx, cb0, cb1, cb2, cb3, out);

    finalize_kernel<<<1, 256>>>(out);
}

// round 3
// speedup vs baseline: 1.0024x; 1.0024x over previous
#include <cuda_runtime.h>

// Problem shapes (fixed by the dataset)
#define B_DIM 64
#define N_DIM 1024
#define C_DIM 256
#define TOK   64      // tokens per block (phase 1)
#define CODE_T 128    // codes per block tile
#define KC    32      // C-chunk staged in smem
#define ZS_STR 68
#define CB_STR 132
#define SMEM_FLOATS (C_DIM * ZS_STR + KC * CB_STR)
#define SMEM_BYTES  (SMEM_FLOATS * 4)
#define EPS_AMB 1e-3f
#define NTOK (B_DIM * N_DIM)
#define OUT_IDX ((size_t)B_DIM * N_DIM * C_DIM)
#define OUT_LOSS (OUT_IDX + (size_t)B_DIM * N_DIM)

// Device scratch (no cudaMalloc allowed)
__device__ float g_cnorm[3840];     // ||c_k||^2 (fp64-accurate, stored fp32)
__device__ float g_partial[1024];   // per-block SSE partials
__device__ int   g_idx[NTOK];       // per-token winning code
__device__ int   g_amb[NTOK];       // ambiguous token list
__device__ int   g_cnt;             // ambiguous count

__device__ __forceinline__ void pick_cb(int e, const float* cb0, const float* cb1,
                                        const float* cb2, const float* cb3,
                                        const float*& cb, int& K, int& coff)
{
    if (e == 0)      { cb = cb0; K = 256;  coff = 0;    }
    else if (e == 1) { cb = cb1; K = 512;  coff = 256;  }
    else if (e == 2) { cb = cb2; K = 1024; coff = 768;  }
    else             { cb = cb3; K = 2048; coff = 1792; }
}

// ---------------------------------------------------------------------------
// K0: codebook row norms in fp64 (rounded to fp32) + reset ambiguous counter
// ---------------------------------------------------------------------------
__global__ void cnorm_kernel(const float* __restrict__ cb0, const float* __restrict__ cb1,
                             const float* __restrict__ cb2, const float* __restrict__ cb3)
{
    if (blockIdx.x == 0 && threadIdx.x == 0) g_cnt = 0;
    int row  = blockIdx.x * 8 + (threadIdx.x >> 5);
    int lane = threadIdx.x & 31;
    const float* base; int local;
    if (row < 256)       { base = cb0; local = row;        }
    else if (row < 768)  { base = cb1; local = row - 256;  }
    else if (row < 1792) { base = cb2; local = row - 768;  }
    else                 { base = cb3; local = row - 1792; }
    const float4* p = (const float4*)(base + (size_t)local * C_DIM);
    double s = 0.0;
    #pragma unroll
    for (int i = 0; i < 2; i++) {
        float4 v = p[lane + i * 32];
        s += (double)v.x * v.x + (double)v.y * v.y + (double)v.z * v.z + (double)v.w * v.w;
    }
    #pragma unroll
    for (int o = 16; o; o >>= 1) s += __shfl_xor_sync(0xffffffffu, s, o);
    if (lane == 0) g_cnorm[row] = (float)s;
}

// ---------------------------------------------------------------------------
// K1: distance GEMM + top-2 argmin per token; flag ambiguous tokens
// ---------------------------------------------------------------------------
__global__ __launch_bounds__(256, 2) void vq_main(
    const float* __restrict__ z_e, const int* __restrict__ expert_idx,
    const float* __restrict__ cb0, const float* __restrict__ cb1,
    const float* __restrict__ cb2, const float* __restrict__ cb3)
{
    extern __shared__ float smem[];
    float* zs  = smem;
    float* cbs = smem + C_DIM * ZS_STR;

    const int tid = threadIdx.x;
    const int b   = blockIdx.y;
    const int t0  = blockIdx.x * TOK;

    const float* cb; int K, coff;
    pick_cb(expert_idx[b], cb0, cb1, cb2, cb3, cb, K, coff);

    const float4* zin = (const float4*)(z_e + ((size_t)b * N_DIM + t0) * C_DIM);

    for (int i = tid; i < TOK * (C_DIM / 4); i += 256) {
        int t = i >> 6, c4 = i & 63;
        float4 v = zin[(size_t)t * 64 + c4];
        int c = c4 * 4;
        zs[(c + 0) * ZS_STR + t] = v.x;
        zs[(c + 1) * ZS_STR + t] = v.y;
        zs[(c + 2) * ZS_STR + t] = v.z;
        zs[(c + 3) * ZS_STR + t] = v.w;
    }

    const int tx = tid & 15, ty = tid >> 4;
    float v1[4] = {3.4e38f, 3.4e38f, 3.4e38f, 3.4e38f};
    float v2[4] = {3.4e38f, 3.4e38f, 3.4e38f, 3.4e38f};
    int   i1[4] = {0, 0, 0, 0};

    for (int k0 = 0; k0 < K; k0 += CODE_T) {
        float acc[4][8];
        #pragma unroll
        for (int i = 0; i < 4; i++)
            #pragma unroll
            for (int j = 0; j < 8; j++) acc[i][j] = 0.f;

        for (int c0 = 0; c0 < C_DIM; c0 += KC) {
            __syncthreads();
            for (int i = tid; i < CODE_T * (KC / 4); i += 256) {
                int kk = i >> 3, c4 = i & 7;
                float4 v = *(const float4*)(cb + (size_t)(k0 + kk) * C_DIM + c0 + c4 * 4);
                int cc = c4 * 4;
                cbs[(cc + 0) * CB_STR + kk] = v.x;
                cbs[(cc + 1) * CB_STR + kk] = v.y;
                cbs[(cc + 2) * CB_STR + kk] = v.z;
                cbs[(cc + 3) * CB_STR + kk] = v.w;
            }
            __syncthreads();

            #pragma unroll
            for (int c = 0; c < KC; c++) {
                float4 rz = *(const float4*)&zs[(c0 + c) * ZS_STR + ty * 4];
                float4 ra = *(const float4*)&cbs[c * CB_STR + tx * 8];
                float4 rb = *(const float4*)&cbs[c * CB_STR + tx * 8 + 4];
                float zz[4] = {rz.x, rz.y, rz.z, rz.w};
                float kv[8] = {ra.x, ra.y, ra.z, ra.w, rb.x, rb.y, rb.z, rb.w};
                #pragma unroll
                for (int i = 0; i < 4; i++)
                    #pragma unroll
                    for (int j = 0; j < 8; j++)
                        acc[i][j] += zz[i] * kv[j];
            }
        }

        #pragma unroll
        for (int j = 0; j < 8; j++) {
            int k = k0 + tx * 8 + j;
            float cn = __ldg(&g_cnorm[coff + k]);
            #pragma unroll
            for (int i = 0; i < 4; i++) {
                float s = cn - 2.f * acc[i][j];
                if (s < v1[i]) { v2[i] = v1[i]; v1[i] = s; i1[i] = k; }
                else if (s < v2[i]) { v2[i] = s; }
            }
        }
    }

    // Merge top-2 across the 16 tx lanes
    #pragma unroll
    for (int o = 8; o; o >>= 1) {
        #pragma unroll
        for (int i = 0; i < 4; i++) {
            float ov1 = __shfl_xor_sync(0xffffffffu, v1[i], o);
            int   oi1 = __shfl_xor_sync(0xffffffffu, i1[i], o);
            float ov2 = __shfl_xor_sync(0xffffffffu, v2[i], o);
            float hi = fmaxf(v1[i], ov1);           // loser of the two mins
            float nv2 = fminf(fminf(v2[i], ov2), hi);
            if (ov1 < v1[i] || (ov1 == v1[i] && oi1 < i1[i])) { v1[i] = ov1; i1[i] = oi1; }
            v2[i] = nv2;
        }
    }
    if (tx == 0) {
        #pragma unroll
        for (int i = 0; i < 4; i++) {
            int tok = b * N_DIM + t0 + ty * 4 + i;
            g_idx[tok] = i1[i];
            if (v2[i] - v1[i] <= EPS_AMB) {
                int pos = atomicAdd(&g_cnt, 1);
                g_amb[pos] = tok;
            }
        }
    }
}

// ---------------------------------------------------------------------------
// K2: resolve ambiguous tokens by emulating the reference fp32 rounding:
//   d_k = fl(fl(zn + cn_k) - 2*dot_k)  ==  zn + RN_Gs(cn_k) - RN_Gd(2*dot_k)
// with dot_k = sequential ascending fp32 FMA chain (Eigen/cublas sgemm order).
// One warp per token; argmin with first-index tie-break.
// ---------------------------------------------------------------------------
__global__ __launch_bounds__(256) void resolve_kernel(
    const float* __restrict__ z_e, const int* __restrict__ expert_idx,
    const float* __restrict__ cb0, const float* __restrict__ cb1,
    const float* __restrict__ cb2, const float* __restrict__ cb3)
{
    __shared__ float zrow[8][C_DIM];
    const int wid = threadIdx.x >> 5, lane = threadIdx.x & 31;
    const int gw = blockIdx.x * 8 + wid;
    const int nw = gridDim.x * 8;
    const int cnt = g_cnt;

    for (int it = gw; it < cnt; it += nw) {
        int tok = g_amb[it];
        int b = tok >> 10;
        const float* cb; int K, coff;
        pick_cb(expert_idx[b], cb0, cb1, cb2, cb3, cb, K, coff);

        const float4* zr = (const float4*)(z_e + (size_t)tok * C_DIM);
        #pragma unroll
        for (int r = 0; r < 2; r++) {
            float4 v = zr[lane + r * 32];
            int c = (lane + r * 32) * 4;
            zrow[wid][c + 0] = v.x; zrow[wid][c + 1] = v.y;
            zrow[wid][c + 2] = v.z; zrow[wid][c + 3] = v.w;
        }
        __syncwarp();

        // zn in fp64 (only its binade matters)
        double zn = 0.0;
        #pragma unroll
        for (int c = 0; c < 8; c++) {
            double z = (double)zrow[wid][lane * 8 + c];
            zn += z * z;
        }
        #pragma unroll
        for (int o = 16; o; o >>= 1) zn += __shfl_xor_sync(0xffffffffu, zn, o);

        const double invGs = (zn >= 256.0) ? 32768.0 : 65536.0;
        const double Gs = 1.0 / invGs;

        double bestm = 1e300; int besti = 0x7fffffff;
        for (int k0 = 0; k0 < K; k0 += 32) {
            int k = k0 + lane;
            const float* cr = cb + (size_t)k * C_DIM;
            float acc = 0.f;
            #pragma unroll 8
            for (int c = 0; c < C_DIM; c++)
                acc = fmaf(zrow[wid][c], __ldg(&cr[c]), acc);  // dependent chain: fixed order
            float cn32 = __ldg(&g_cnorm[coff + k]);
            double dot2 = 2.0 * (double)acc;
            double d = zn + (double)cn32 - dot2;
            double invGd = (d >= 256.0) ? 32768.0 : 65536.0;
            double Gd = 1.0 / invGd;
            double m = rint((double)cn32 * invGs) * Gs - rint(dot2 * invGd) * Gd;
            if (m < bestm || (m == bestm && k < besti)) { bestm = m; besti = k; }
        }
        #pragma unroll
        for (int o = 16; o; o >>= 1) {
            double om = __shfl_xor_sync(0xffffffffu, bestm, o);
            int    oi = __shfl_xor_sync(0xffffffffu, besti, o);
            if (om < bestm || (om == bestm && oi < besti)) { bestm = om; besti = oi; }
        }
        if (lane == 0) g_idx[tok] = besti;
    }
}

// ---------------------------------------------------------------------------
// K3: gather z_q, straight-through rounding, indices output, SSE partials
// ---------------------------------------------------------------------------
__global__ __launch_bounds__(256) void output_kernel(
    const float* __restrict__ z_e, const int* __restrict__ expert_idx,
    const float* __restrict__ cb0, const float* __restrict__ cb1,
    const float* __restrict__ cb2, const float* __restrict__ cb3,
    float* __restrict__ out)
{
    __shared__ float wsum[8];
    const int tid = threadIdx.x;
    const int b   = blockIdx.y;
    const int t0  = blockIdx.x * TOK;

    const float* cb; int K, coff;
    pick_cb(expert_idx[b], cb0, cb1, cb2, cb3, cb, K, coff);

    const float4* zin = (const float4*)(z_e + ((size_t)b * N_DIM + t0) * C_DIM);

    if (tid < TOK) {
        int idx = g_idx[b * N_DIM + t0 + tid];
        out[OUT_IDX + (size_t)b * N_DIM + t0 + tid] = (float)idx;
    }

    const int warp = tid >> 5, lane = tid & 31;
    float sq = 0.f;
    for (int s8 = 0; s8 < 8; s8++) {
        int t = warp * 8 + s8;
        int idx = g_idx[b * N_DIM + t0 + t];
        const float4* crow = (const float4*)(cb + (size_t)idx * C_DIM);
        const float4* zrow = zin + (size_t)t * 64;
        float4* orow = (float4*)(out + ((size_t)b * N_DIM + t0 + t) * C_DIM);
        #pragma unroll
        for (int r = 0; r < 2; r++) {
            int c4 = lane + r * 32;
            float4 q = crow[c4], z = zrow[c4];
            float dx = q.x - z.x, dy = q.y - z.y, dz = q.z - z.z, dw = q.w - z.w;
            sq += dx * dx + dy * dy + dz * dz + dw * dw;
            float4 o; o.x = z.x + dx; o.y = z.y + dy; o.z = z.z + dz; o.w = z.w + dw;
            orow[c4] = o;
        }
    }
    #pragma unroll
    for (int o = 16; o; o >>= 1) sq += __shfl_xor_sync(0xffffffffu, sq, o);
    if (lane == 0) wsum[warp] = sq;
    __syncthreads();
    if (tid == 0) {
        float tot = 0.f;
        #pragma unroll
        for (int w = 0; w < 8; w++) tot += wsum[w];
        g_partial[blockIdx.y * 16 + blockIdx.x] = tot;
    }
}

// ---------------------------------------------------------------------------
// K4: vq_loss = 1.25 * SSE / 2^32
// ---------------------------------------------------------------------------
__global__ void finalize_kernel(float* __restrict__ out)
{
    __shared__ float s[256];
    float a = 0.f;
    for (int i = threadIdx.x; i < 1024; i += 256) a += g_partial[i];
    s[threadIdx.x] = a;
    __syncthreads();
    for (int o = 128; o; o >>= 1) {
        if (threadIdx.x < o) s[threadIdx.x] += s[threadIdx.x + o];
        __syncthreads();
    }
    if (threadIdx.x == 0)
        out[OUT_LOSS] = s[0] * (float)(1.25 / 4294967296.0);
}

// ---------------------------------------------------------------------------
extern "C" void kernel_launch(void* const* d_in, const int* in_sizes, int n_in,
                              void* d_out, int out_size)
{
    const float* z_e        = (const float*)d_in[0];
    const int*   expert_idx = (const int*)  d_in[1];
    const float* cb0        = (const float*)d_in[2];
    const float* cb1        = (const float*)d_in[3];
    const float* cb2        = (const float*)d_in[4];
    const float* cb3        = (const float*)d_in[5];
    float* out = (float*)d_out;

    cudaFuncSetAttribute(vq_main, cudaFuncAttributeMaxDynamicSharedMemorySize, SMEM_BYTES);

    cnorm_kernel<<<3840 / 8, 256>>>(cb0, cb1, cb2, cb3);

    dim3 grid(N_DIM / TOK, B_DIM);
    vq_main<<<grid, 256, SMEM_BYTES>>>(z_e, expert_idx, cb0, cb1, cb2, cb3);

    resolve_kernel<<<128, 256>>>(z_e, expert_idx, cb0, cb1, cb2, cb3);

    output_kernel<<<grid, 256>>>(z_e, expert_idx, cb0, cb1, cb2, cb3, out);

    finalize_kernel<<<1, 256>>>(out);
}

// round 6
// speedup vs baseline: 1.4563x; 1.4528x over previous
#include <cuda_runtime.h>
#include <cuda_bf16.h>
#include <cstdint>

#define B_DIM 64
#define N_DIM 1024
#define C_DIM 256
#define NTOK (B_DIM * N_DIM)
#define OUT_IDX  ((size_t)B_DIM * N_DIM * C_DIM)
#define OUT_LOSS (OUT_IDX + (size_t)B_DIM * N_DIM)
#define EPS_AMB 1e-3f
#define TOK 64
#define MT 128            // tokens per CTA
#define NT 32             // codes per chunk

// padded bf16 row stride: 264 elems = 528B (16B-aligned, ldmatrix conflict-free)
#define A_STR_B 528
#define SM_AHI 0
#define SM_ALO (MT * A_STR_B)          // 67584
#define SM_B   (2 * MT * A_STR_B)      // 135168
#define B_PLANE (NT * A_STR_B)         // 16896
#define B_BUF   (2 * B_PLANE)          // 33792 (hi+lo)
#define SM_DYN  (SM_B + 2 * B_BUF)     // 202752

// ---- device scratch (no cudaMalloc allowed) ----
__device__ float g_cnorm[3840];
__device__ float g_partial[1024];
__device__ int   g_idx[NTOK];
__device__ int   g_amb[NTOK];
__device__ int   g_cnt;
__device__ __nv_bfloat16 g_cbh[3840 * 256];
__device__ __nv_bfloat16 g_cbl[3840 * 256];

// ---- helpers ----
__device__ __forceinline__ uint32_t smem_u32(const void* p) {
    uint32_t a;
    asm("{ .reg .u64 t; cvta.to.shared.u64 t, %1; cvt.u32.u64 %0, t; }" : "=r"(a) : "l"(p));
    return a;
}
#define CP16(dst, src)  asm volatile("cp.async.cg.shared.global [%0], [%1], 16;" :: "r"(dst), "l"(src) : "memory")
#define CP_COMMIT()     asm volatile("cp.async.commit_group;" ::: "memory")

#define LDM_X4(r0, r1, r2, r3, addr) \
    asm volatile("ldmatrix.sync.aligned.m8n8.x4.shared.b16 {%0,%1,%2,%3}, [%4];" \
        : "=r"(r0), "=r"(r1), "=r"(r2), "=r"(r3) : "r"(addr))

#define MMA16816(c0, c1, c2, c3, a0, a1, a2, a3, b0, b1) \
    asm volatile("mma.sync.aligned.m16n8k16.row.col.f32.bf16.bf16.f32 " \
        "{%0,%1,%2,%3}, {%4,%5,%6,%7}, {%8,%9}, {%0,%1,%2,%3};" \
        : "+f"(c0), "+f"(c1), "+f"(c2), "+f"(c3) \
        : "r"(a0), "r"(a1), "r"(a2), "r"(a3), "r"(b0), "r"(b1))

__device__ __forceinline__ void pick_cb(int e, const float* cb0, const float* cb1,
                                        const float* cb2, const float* cb3,
                                        const float*& cb, int& K, int& coff) {
    if (e == 0)      { cb = cb0; K = 256;  coff = 0;    }
    else if (e == 1) { cb = cb1; K = 512;  coff = 256;  }
    else if (e == 2) { cb = cb2; K = 1024; coff = 768;  }
    else             { cb = cb3; K = 2048; coff = 1792; }
}

// ---------------------------------------------------------------------------
// K0a: codebooks -> bf16 hi/lo planes
// ---------------------------------------------------------------------------
__global__ void convert_kernel(const float* __restrict__ cb0, const float* __restrict__ cb1,
                               const float* __restrict__ cb2, const float* __restrict__ cb3)
{
    int idx = blockIdx.x * 256 + threadIdx.x;     // one float4 each; 3840*64 total
    int row = idx >> 6, c4 = idx & 63;
    const float* base; int local;
    if (row < 256)       { base = cb0; local = row;        }
    else if (row < 768)  { base = cb1; local = row - 256;  }
    else if (row < 1792) { base = cb2; local = row - 768;  }
    else                 { base = cb3; local = row - 1792; }
    float4 v = ((const float4*)(base + (size_t)local * C_DIM))[c4];
    float x[4] = {v.x, v.y, v.z, v.w};
    size_t o = (size_t)row * 256 + c4 * 4;
    #pragma unroll
    for (int i = 0; i < 4; i++) {
        __nv_bfloat16 h = __float2bfloat16(x[i]);
        __nv_bfloat16 l = __float2bfloat16(x[i] - __bfloat162float(h));
        g_cbh[o + i] = h;
        g_cbl[o + i] = l;
    }
}

// ---------------------------------------------------------------------------
// K0b: codebook row norms (fp64 -> fp32) + reset ambiguous counter
// ---------------------------------------------------------------------------
__global__ void cnorm_kernel(const float* __restrict__ cb0, const float* __restrict__ cb1,
                             const float* __restrict__ cb2, const float* __restrict__ cb3)
{
    if (blockIdx.x == 0 && threadIdx.x == 0) g_cnt = 0;
    int row  = blockIdx.x * 8 + (threadIdx.x >> 5);
    int lane = threadIdx.x & 31;
    const float* base; int local;
    if (row < 256)       { base = cb0; local = row;        }
    else if (row < 768)  { base = cb1; local = row - 256;  }
    else if (row < 1792) { base = cb2; local = row - 768;  }
    else                 { base = cb3; local = row - 1792; }
    const float4* p = (const float4*)(base + (size_t)local * C_DIM);
    double s = 0.0;
    #pragma unroll
    for (int i = 0; i < 2; i++) {
        float4 v = p[lane + i * 32];
        s += (double)v.x * v.x + (double)v.y * v.y + (double)v.z * v.z + (double)v.w * v.w;
    }
    #pragma unroll
    for (int o = 16; o; o >>= 1) s += __shfl_xor_sync(0xffffffffu, s, o);
    if (lane == 0) g_cnorm[row] = (float)s;
}

// ---------------------------------------------------------------------------
// K1: warp-level mma.sync split-bf16 distance GEMM + top-2 + ambiguity flags.
// CTA: 128 tokens x full K. 8 warps, each 16 tokens x 32 codes per chunk.
// score(k) = ||c_k||^2 - 2 * (zh.ch + zh.cl + zl.ch)
// ---------------------------------------------------------------------------
__global__ __launch_bounds__(256, 1) void vq_mma(
    const float* __restrict__ z_e, const int* __restrict__ expert_idx)
{
    extern __shared__ __align__(16) char dsm[];
    const uint32_t sa = smem_u32(dsm);

    const int tid = threadIdx.x, wid = tid >> 5, lane = tid & 31;
    const int b = blockIdx.y, t0 = blockIdx.x * MT;

    int e = expert_idx[b];
    int K, coff;
    if (e == 0)      { K = 256;  coff = 0;    }
    else if (e == 1) { K = 512;  coff = 256;  }
    else if (e == 2) { K = 1024; coff = 768;  }
    else             { K = 2048; coff = 1792; }

    // ---- stage A: z tile -> bf16 hi/lo, padded 528B rows ----
    const float4* zin = (const float4*)(z_e + ((size_t)b * N_DIM + t0) * C_DIM);
    for (int idx = tid; idx < MT * 64; idx += 256) {
        int t = idx >> 6, c4 = idx & 63;
        float4 v = zin[(size_t)t * 64 + c4];
        float x[4] = {v.x, v.y, v.z, v.w};
        __nv_bfloat16 h[4], l[4];
        #pragma unroll
        for (int i = 0; i < 4; i++) {
            h[i] = __float2bfloat16(x[i]);
            l[i] = __float2bfloat16(x[i] - __bfloat162float(h[i]));
        }
        __nv_bfloat162 hh0, hh1, ll0, ll1;
        hh0.x = h[0]; hh0.y = h[1]; hh1.x = h[2]; hh1.y = h[3];
        ll0.x = l[0]; ll0.y = l[1]; ll1.x = l[2]; ll1.y = l[3];
        char* pa = dsm + t * A_STR_B + c4 * 8;
        *(__nv_bfloat162*)(pa + SM_AHI)     = hh0;
        *(__nv_bfloat162*)(pa + SM_AHI + 4) = hh1;
        *(__nv_bfloat162*)(pa + SM_ALO)     = ll0;
        *(__nv_bfloat162*)(pa + SM_ALO + 4) = ll1;
    }

    // ---- B chunk stage: 2 planes x 32 rows x 32 x 16B segs = full 512B rows ----
    auto stageB = [&](int chunk) {
        int kbase = coff + chunk * NT;
        uint32_t dbuf = sa + SM_B + (uint32_t)(chunk & 1) * B_BUF;
        #pragma unroll
        for (int it = 0; it < 8; it++) {
            int idx = tid + it * 256;          // 0..2047
            int plane = idx >> 10;             // 0: hi, 1: lo
            int n = (idx >> 5) & 31;
            int seg = idx & 31;                // 32 segs x 16B = 512B/row
            const __nv_bfloat16* src =
                (plane ? g_cbl : g_cbh) + (size_t)(kbase + n) * 256 + seg * 8;
            uint32_t dst = dbuf + (uint32_t)plane * B_PLANE + n * A_STR_B + seg * 16;
            CP16(dst, src);
        }
    };

    stageB(0);
    CP_COMMIT();

    const int m0 = wid * 16;
    const int g = lane >> 2, tq = lane & 3;
    float v1[2] = {3.4e38f, 3.4e38f}, v2[2] = {3.4e38f, 3.4e38f};
    int   i1[2] = {0, 0};

    // lane-fixed ldmatrix address components
    const uint32_t a_lbase = sa + (m0 + (lane & 15)) * A_STR_B + ((lane >> 4) & 1) * 16;
    const uint32_t b_row   = ((lane >> 4) & 1) * 8 + (lane & 7);
    const uint32_t b_koff  = ((lane >> 3) & 1) * 16;

    const int nch = K / NT;
    for (int i = 0; i < nch; i++) {
        if (i + 1 < nch) {
            stageB(i + 1);
            CP_COMMIT();
            asm volatile("cp.async.wait_group 1;" ::: "memory");
        } else {
            asm volatile("cp.async.wait_group 0;" ::: "memory");
        }
        __syncthreads();   // buffer (i&1) ready for all; A staged (first iter)

        const uint32_t Bb = sa + SM_B + (uint32_t)(i & 1) * B_BUF;
        float c0[4] = {0,0,0,0}, c1[4] = {0,0,0,0}, c2[4] = {0,0,0,0}, c3[4] = {0,0,0,0};

        #pragma unroll
        for (int ks = 0; ks < 16; ks++) {
            uint32_t ah0,ah1,ah2,ah3, al0,al1,al2,al3;
            LDM_X4(ah0,ah1,ah2,ah3, a_lbase + SM_AHI + ks * 32);
            LDM_X4(al0,al1,al2,al3, a_lbase + SM_ALO + ks * 32);

            #pragma unroll
            for (int p = 0; p < 2; p++) {
                uint32_t baddr = Bb + (p * 16 + b_row) * A_STR_B + b_koff + ks * 32;
                uint32_t bh0,bh1,bh2,bh3, bl0,bl1,bl2,bl3;
                LDM_X4(bh0,bh1,bh2,bh3, baddr);
                LDM_X4(bl0,bl1,bl2,bl3, baddr + B_PLANE);
                float* ca = p ? c2 : c0;
                float* cb = p ? c3 : c1;
                MMA16816(ca[0],ca[1],ca[2],ca[3], ah0,ah1,ah2,ah3, bh0,bh1);
                MMA16816(ca[0],ca[1],ca[2],ca[3], ah0,ah1,ah2,ah3, bl0,bl1);
                MMA16816(ca[0],ca[1],ca[2],ca[3], al0,al1,al2,al3, bh0,bh1);
                MMA16816(cb[0],cb[1],cb[2],cb[3], ah0,ah1,ah2,ah3, bh2,bh3);
                MMA16816(cb[0],cb[1],cb[2],cb[3], ah0,ah1,ah2,ah3, bl2,bl3);
                MMA16816(cb[0],cb[1],cb[2],cb[3], al0,al1,al2,al3, bh2,bh3);
            }
        }

        // epilogue: scores for 4 n-tiles; lane covers rows (g, g+8), cols (2tq, 2tq+1)
        float* cc[4] = {c0, c1, c2, c3};
        #pragma unroll
        for (int j = 0; j < 4; j++) {
            int n0 = i * NT + j * 8 + tq * 2;
            float2 cn = __ldg((const float2*)(g_cnorm + coff + n0));
            float s00 = fmaf(-2.f, cc[j][0], cn.x);
            float s01 = fmaf(-2.f, cc[j][1], cn.y);
            float s10 = fmaf(-2.f, cc[j][2], cn.x);
            float s11 = fmaf(-2.f, cc[j][3], cn.y);
            if (s00 < v1[0]) { v2[0] = v1[0]; v1[0] = s00; i1[0] = n0; }     else v2[0] = fminf(v2[0], s00);
            if (s01 < v1[0]) { v2[0] = v1[0]; v1[0] = s01; i1[0] = n0 + 1; } else v2[0] = fminf(v2[0], s01);
            if (s10 < v1[1]) { v2[1] = v1[1]; v1[1] = s10; i1[1] = n0; }     else v2[1] = fminf(v2[1], s10);
            if (s11 < v1[1]) { v2[1] = v1[1]; v1[1] = s11; i1[1] = n0 + 1; } else v2[1] = fminf(v2[1], s11);
        }
        __syncthreads();   // all warps done with buffer before next prefetch overwrite
    }

    // merge top-2 across the 4 lanes of each quad (same g)
    #pragma unroll
    for (int o = 1; o <= 2; o <<= 1) {
        #pragma unroll
        for (int r = 0; r < 2; r++) {
            float ov1 = __shfl_xor_sync(0xffffffffu, v1[r], o);
            int   oi1 = __shfl_xor_sync(0xffffffffu, i1[r], o);
            float ov2 = __shfl_xor_sync(0xffffffffu, v2[r], o);
            float hi = fmaxf(v1[r], ov1);
            float nv2 = fminf(fminf(v2[r], ov2), hi);
            if (ov1 < v1[r] || (ov1 == v1[r] && oi1 < i1[r])) { v1[r] = ov1; i1[r] = oi1; }
            v2[r] = nv2;
        }
    }
    if (tq == 0) {
        #pragma unroll
        for (int r = 0; r < 2; r++) {
            int tok = b * N_DIM + t0 + m0 + g + r * 8;
            g_idx[tok] = i1[r];
            if (v2[r] - v1[r] <= EPS_AMB) {
                int pos = atomicAdd(&g_cnt, 1);
                g_amb[pos] = tok;
            }
        }
    }
}

// ---------------------------------------------------------------------------
// K2: exact resolver (validated round 2): emulate reference fp32 rounding
//   d_k = fl(fl(zn + cn_k) - 2*dot_k) == zn + RN_Gs(cn_k) - RN_Gd(2*dot_k)
// with dot_k = sequential fp32 FMA chain. One warp per token.
// ---------------------------------------------------------------------------
__global__ __launch_bounds__(256) void resolve_kernel(
    const float* __restrict__ z_e, const int* __restrict__ expert_idx,
    const float* __restrict__ cb0, const float* __restrict__ cb1,
    const float* __restrict__ cb2, const float* __restrict__ cb3)
{
    __shared__ float zrow[8][C_DIM];
    const int wid = threadIdx.x >> 5, lane = threadIdx.x & 31;
    const int gw = blockIdx.x * 8 + wid;
    const int nw = gridDim.x * 8;
    const int cnt = g_cnt;

    for (int it = gw; it < cnt; it += nw) {
        int tok = g_amb[it];
        int b = tok >> 10;
        const float* cb; int K, coff;
        pick_cb(expert_idx[b], cb0, cb1, cb2, cb3, cb, K, coff);

        const float4* zr = (const float4*)(z_e + (size_t)tok * C_DIM);
        #pragma unroll
        for (int r = 0; r < 2; r++) {
            float4 v = zr[lane + r * 32];
            int c = (lane + r * 32) * 4;
            zrow[wid][c + 0] = v.x; zrow[wid][c + 1] = v.y;
            zrow[wid][c + 2] = v.z; zrow[wid][c + 3] = v.w;
        }
        __syncwarp();

        double zn = 0.0;
        #pragma unroll
        for (int c = 0; c < 8; c++) {
            double z = (double)zrow[wid][lane * 8 + c];
            zn += z * z;
        }
        #pragma unroll
        for (int o = 16; o; o >>= 1) zn += __shfl_xor_sync(0xffffffffu, zn, o);

        const double invGs = (zn >= 256.0) ? 32768.0 : 65536.0;
        const double Gs = 1.0 / invGs;

        double bestm = 1e300; int besti = 0x7fffffff;
        for (int k0 = 0; k0 < K; k0 += 32) {
            int k = k0 + lane;
            const float* cr = cb + (size_t)k * C_DIM;
            float acc = 0.f;
            #pragma unroll 8
            for (int c = 0; c < C_DIM; c++)
                acc = fmaf(zrow[wid][c], __ldg(&cr[c]), acc);
            float cn32 = __ldg(&g_cnorm[coff + k]);
            double dot2 = 2.0 * (double)acc;
            double d = zn + (double)cn32 - dot2;
            double invGd = (d >= 256.0) ? 32768.0 : 65536.0;
            double Gd = 1.0 / invGd;
            double m = rint((double)cn32 * invGs) * Gs - rint(dot2 * invGd) * Gd;
            if (m < bestm || (m == bestm && k < besti)) { bestm = m; besti = k; }
        }
        #pragma unroll
        for (int o = 16; o; o >>= 1) {
            double om = __shfl_xor_sync(0xffffffffu, bestm, o);
            int    oi = __shfl_xor_sync(0xffffffffu, besti, o);
            if (om < bestm || (om == bestm && oi < besti)) { bestm = om; besti = oi; }
        }
        if (lane == 0) g_idx[tok] = besti;
    }
}

// ---------------------------------------------------------------------------
// K3: gather z_q, straight-through, indices output, SSE partials
// ---------------------------------------------------------------------------
__global__ __launch_bounds__(256) void output_kernel(
    const float* __restrict__ z_e, const int* __restrict__ expert_idx,
    const float* __restrict__ cb0, const float* __restrict__ cb1,
    const float* __restrict__ cb2, const float* __restrict__ cb3,
    float* __restrict__ out)
{
    __shared__ float wsum[8];
    const int tid = threadIdx.x;
    const int b   = blockIdx.y;
    const int t0  = blockIdx.x * TOK;

    const float* cb; int K, coff;
    pick_cb(expert_idx[b], cb0, cb1, cb2, cb3, cb, K, coff);

    const float4* zin = (const float4*)(z_e + ((size_t)b * N_DIM + t0) * C_DIM);

    if (tid < TOK) {
        int idx = g_idx[b * N_DIM + t0 + tid];
        out[OUT_IDX + (size_t)b * N_DIM + t0 + tid] = (float)idx;
    }

    const int warp = tid >> 5, lane = tid & 31;
    float sq = 0.f;
    for (int s8 = 0; s8 < 8; s8++) {
        int t = warp * 8 + s8;
        int idx = g_idx[b * N_DIM + t0 + t];
        const float4* crow = (const float4*)(cb + (size_t)idx * C_DIM);
        const float4* zrow = zin + (size_t)t * 64;
        float4* orow = (float4*)(out + ((size_t)b * N_DIM + t0 + t) * C_DIM);
        #pragma unroll
        for (int r = 0; r < 2; r++) {
            int c4 = lane + r * 32;
            float4 q = crow[c4], z = zrow[c4];
            float dx = q.x - z.x, dy = q.y - z.y, dz = q.z - z.z, dw = q.w - z.w;
            sq += dx * dx + dy * dy + dz * dz + dw * dw;
            float4 o; o.x = z.x + dx; o.y = z.y + dy; o.z = z.z + dz; o.w = z.w + dw;
            orow[c4] = o;
        }
    }
    #pragma unroll
    for (int o = 16; o; o >>= 1) sq += __shfl_xor_sync(0xffffffffu, sq, o);
    if (lane == 0) wsum[warp] = sq;
    __syncthreads();
    if (tid == 0) {
        float tot = 0.f;
        #pragma unroll
        for (int w = 0; w < 8; w++) tot += wsum[w];
        g_partial[blockIdx.y * 16 + blockIdx.x] = tot;
    }
}

// ---------------------------------------------------------------------------
// K4: vq_loss = 1.25 * SSE / 2^32
// ---------------------------------------------------------------------------
__global__ void finalize_kernel(float* __restrict__ out)
{
    __shared__ float s[256];
    float a = 0.f;
    for (int i = threadIdx.x; i < 1024; i += 256) a += g_partial[i];
    s[threadIdx.x] = a;
    __syncthreads();
    for (int o = 128; o; o >>= 1) {
        if (threadIdx.x < o) s[threadIdx.x] += s[threadIdx.x + o];
        __syncthreads();
    }
    if (threadIdx.x == 0)
        out[OUT_LOSS] = s[0] * (float)(1.25 / 4294967296.0);
}

// ---------------------------------------------------------------------------
extern "C" void kernel_launch(void* const* d_in, const int* in_sizes, int n_in,
                              void* d_out, int out_size)
{
    const float* z_e        = (const float*)d_in[0];
    const int*   expert_idx = (const int*)  d_in[1];
    const float* cb0        = (const float*)d_in[2];
    const float* cb1        = (const float*)d_in[3];
    const float* cb2        = (const float*)d_in[4];
    const float* cb3        = (const float*)d_in[5];
    float* out = (float*)d_out;

    cudaFuncSetAttribute(vq_mma, cudaFuncAttributeMaxDynamicSharedMemorySize, SM_DYN);

    convert_kernel<<<960, 256>>>(cb0, cb1, cb2, cb3);
    cnorm_kernel<<<480, 256>>>(cb0, cb1, cb2, cb3);

    dim3 gmma(N_DIM / MT, B_DIM);
    vq_mma<<<gmma, 256, SM_DYN>>>(z_e, expert_idx);

    resolve_kernel<<<128, 256>>>(z_e, expert_idx, cb0, cb1, cb2, cb3);

    dim3 gout(N_DIM / TOK, B_DIM);
    output_kernel<<<gout, 256>>>(z_e, expert_idx, cb0, cb1, cb2, cb3, out);

    finalize_kernel<<<1, 256>>>(out);
}